// round 7
// baseline (speedup 1.0000x reference)
#include <cuda_runtime.h>
#include <cstdint>

// CTC forward loss, B=32, T=2048, V=1024, S=256. Single kernel.
// 16 CTAs x 512 threads: each CTA co-schedules TWO batches (half h = tid>>8),
// giving 4 warps/SMSP for latency hiding. Within a half (256 threads),
// thread i owns ext positions 2i+1 (token, aT) and 2i+2 (blank, aB);
// thread 0 also position 0 (a0, pure add). Neighbors via shfl_up; warp
// boundaries through 8 smem slots (parity double-buffered).
// Uniform t=1..2047 loop; per-half warp-uniform "t < Tl" branch.
// Log-prob rows streamed per half via 8-stage cp.async pipeline.
// Loss reduction folded in (last-block pattern, deterministic order).

#define TT 2048
#define VV 1024
#define SS 256
#define BB 32
#define NEGF (-1e30f)
#define STAGES 8
#define NTHREADS 512
#define NCTAS 16

__device__ float g_losses[BB];
__device__ unsigned int g_done;   // zero-init; self-resetting

__device__ __forceinline__ void cp_async16(uint32_t smem_addr, const void* gmem) {
    asm volatile("cp.async.cg.shared.global [%0], [%1], 16;\n"
                 :: "r"(smem_addr), "l"(gmem));
}
__device__ __forceinline__ void cp_commit() {
    asm volatile("cp.async.commit_group;\n" ::: "memory");
}
template <int N>
__device__ __forceinline__ void cp_wait() {
    asm volatile("cp.async.wait_group %0;\n" :: "n"(N) : "memory");
}

// LSE2: m + log(1 + e^(lo-m))  (max term's exp == 1)
__device__ __forceinline__ float lse2(float a, float b) {
    const float m  = fmaxf(a, b);
    const float lo = fminf(a, b);
    return m + __logf(1.0f + __expf(lo - m));
}
// LSE3 with max term's exp folded into the constant 1.
__device__ __forceinline__ float lse3(float x0, float x1, float x2) {
    const float lo1 = fminf(x0, x1);
    const float hi1 = fmaxf(x0, x1);
    const float m   = fmaxf(hi1, x2);
    const float o2  = fminf(hi1, x2);
    return m + __logf(1.0f + __expf(lo1 - m) + __expf(o2 - m));
}

__global__ void __launch_bounds__(NTHREADS, 1)
ctc_fused(const float* __restrict__ lp,     // [B, T, V] log-probs
          const int* __restrict__ tok,      // [B, S]
          const int* __restrict__ tlens,    // [B]
          const int* __restrict__ slens,    // [B]
          float* __restrict__ out) {
    extern __shared__ float smem[];         // [2][STAGES][VV] rows + bnd

    const int tid  = threadIdx.x;
    const int h    = tid >> 8;              // half (batch within CTA)
    const int lt   = tid & 255;             // local tid within half
    const int lane = tid & 31;
    const int wh   = lt >> 5;               // warp within half, 0..7
    const int b    = (blockIdx.x << 1) + h;

    float* rows = smem + h * (STAGES * VV);
    float* bnd  = smem + 2 * (STAGES * VV) + h * 32;  // [parity][wh][2]

    const int Tl = tlens[b];
    const int Sl = slens[b];
    const float* lpb = lp + (size_t)b * TT * VV;

    const int  Li  = tok[b * SS + lt];
    const bool rep = (lt > 0) && (Li != tok[b * SS + lt - 1]);

    // Prologue: stream rows 0..7, one commit group per row.
    #pragma unroll
    for (int st = 0; st < STAGES; ++st) {
        cp_async16((uint32_t)__cvta_generic_to_shared(rows + st * VV + lt * 4),
                   lpb + (size_t)st * VV + lt * 4);
        cp_commit();
    }
    cp_wait<4>();            // rows 0..3 resident
    __syncthreads();

    // t = 0 init.
    float aT = (lt == 0) ? rows[Li] : NEGF;
    float aB = NEGF;
    float a0 = rows[0];                      // alpha[0], thread lt==0 only

    // Emit regs: (eT,eB) row t, (eTn,eBn) row t+1; prefetch 2 ahead.
    float eT  = rows[VV + Li],     eB  = rows[VV];
    float eTn = rows[2 * VV + Li], eBn = rows[2 * VV];

    if (lane == 31) { bnd[wh * 2 + 0] = aT; bnd[wh * 2 + 1] = aB; }  // parity 0
    __syncthreads();

    for (int t = 1; t < TT; ++t) {
        const int pa = (t - 1) & 1;
        const int pb = t & 1;

        if (t < Tl) {        // warp-uniform per half
            float pT = __shfl_up_sync(0xffffffffu, aT, 1);
            float pB = __shfl_up_sync(0xffffffffu, aB, 1);
            if (lane == 0) {
                if (wh) { pT = bnd[pa * 16 + (wh - 1) * 2 + 0];
                          pB = bnd[pa * 16 + (wh - 1) * 2 + 1]; }
                else    { pT = NEGF; pB = a0; }
            }
            const float nT = eT + lse3(aT, pB, rep ? pT : NEGF);
            const float nB = eB + lse2(aB, aT);
            if (lt == 0) a0 = eB + a0;
            aT = nT; aB = nB;
            if (lane == 31) { bnd[pb * 16 + wh * 2 + 0] = aT;
                              bnd[pb * 16 + wh * 2 + 1] = aB; }
            // Rotate emits; prefetch row t+2 (resident via wait<4>).
            eT = eTn; eB = eBn;
            const int sE = (t + 2) & (STAGES - 1);
            eTn = rows[sE * VV + Li];
            eBn = rows[sE * VV];
        }

        // Stream row t+STAGES-1 (skip past end; commit group always).
        {
            const int rW = t + STAGES - 1;
            if (rW < TT) {
                const int sW = rW & (STAGES - 1);
                cp_async16((uint32_t)__cvta_generic_to_shared(rows + sW * VV + lt * 4),
                           lpb + (size_t)rW * VV + lt * 4);
            }
        }
        cp_commit();
        cp_wait<4>();
        __syncthreads();
    }

    // Loss: thread lt = Sl-1 holds alpha[2Sl-1]=aT, alpha[2Sl]=aB.
    if (lt == Sl - 1) {
        float loss = -lse2(aB, aT);
        if (loss > 1e29f) loss = 0.0f;
        g_losses[b] = loss / (float)Sl;
        __threadfence();
    }
    __syncthreads();

    // Last-block deterministic reduction (fixed order, self-resetting flag).
    if (tid == 0) {
        __threadfence();
        const unsigned v = atomicAdd(&g_done, 1u);
        if (v == NCTAS - 1) {
            __threadfence();
            float acc = 0.0f;
            #pragma unroll
            for (int i = 0; i < BB; ++i) acc += g_losses[i];
            out[0] = acc / (float)BB;
            atomicExch(&g_done, 0u);
        }
    }
}

extern "C" void kernel_launch(void* const* d_in, const int* in_sizes, int n_in,
                              void* d_out, int out_size) {
    const float* lp    = (const float*)d_in[0];  // [B,T,V] f32
    const int*   tok   = (const int*)d_in[1];    // [B,S]   i32
    const int*   tlens = (const int*)d_in[2];    // [B]     i32
    const int*   slens = (const int*)d_in[3];    // [B]     i32
    float* out = (float*)d_out;

    // 2 row pipelines (2 * 8 * 4KB) + boundary slots.
    const int smem_bytes = 2 * STAGES * VV * (int)sizeof(float) + 256;
    cudaFuncSetAttribute(ctc_fused, cudaFuncAttributeMaxDynamicSharedMemorySize,
                         smem_bytes);
    ctc_fused<<<NCTAS, NTHREADS, smem_bytes>>>(lp, tok, tlens, slens, out);
}

// round 8
// speedup vs baseline: 1.2212x; 1.2212x over previous
#include <cuda_runtime.h>
#include <cstdint>

// CTC forward loss, B=32, T=2048, V=1024, S=256. Single kernel.
// 32 CTAs x 128 threads (4 warps). NO per-step barrier:
// pairs k=(token s=2k+1, blank s=2k+2), k=0..255. Warp w owns pairs
// [64w,64w+64) in regs r=1,2 and redundantly computes a 32-pair halo
// [64w-32,64w) in reg r=0 (left neighbor's top pairs). Contamination
// advances 1 pair/step, so own pairs stay exact for 32 steps; warps
// refresh halos from the left neighbor's exact registers every CHUNK=16
// steps at a single barrier that also publishes the next 16-row
// cp.async chunk. All per-step exchange is intra-warp shfl.
// Warp 0 maintains a0 (ext position 0, pure add) in registers.

#define TT 2048
#define VV 1024
#define SS 256
#define BB 32
#define NEGF (-1e30f)
#define CHUNK 16
#define NTHREADS 128

__device__ float g_losses[BB];
__device__ unsigned int g_done;   // zero-init; self-resetting

__device__ __forceinline__ void cp_async16(uint32_t smem_addr, const void* gmem) {
    asm volatile("cp.async.cg.shared.global [%0], [%1], 16;\n"
                 :: "r"(smem_addr), "l"(gmem));
}
__device__ __forceinline__ void cp_commit() {
    asm volatile("cp.async.commit_group;\n" ::: "memory");
}
template <int N>
__device__ __forceinline__ void cp_wait() {
    asm volatile("cp.async.wait_group %0;\n" :: "n"(N) : "memory");
}

// LSE2: m + log(1 + e^(lo-m))  (max term's exp == 1)
__device__ __forceinline__ float lse2(float a, float b) {
    const float m  = fmaxf(a, b);
    const float lo = fminf(a, b);
    return m + __logf(1.0f + __expf(lo - m));
}
// LSE3 with max term's exp folded into the constant 1.
__device__ __forceinline__ float lse3(float x0, float x1, float x2) {
    const float lo1 = fminf(x0, x1);
    const float hi1 = fmaxf(x0, x1);
    const float m   = fmaxf(hi1, x2);
    const float o2  = fminf(hi1, x2);
    return m + __logf(1.0f + __expf(lo1 - m) + __expf(o2 - m));
}

// One DP step for this thread's 3 pairs. rowp = log-prob row for time t.
__device__ __forceinline__ void ctc_step(
    const float* __restrict__ rowp,
    float aT[3], float aB[3], float& a0,
    const int L[3], const bool rep[3], const int w, const int lane)
{
    const float eB = rowp[0];
    float eT[3];
    eT[0] = rowp[L[0]]; eT[1] = rowp[L[1]]; eT[2] = rowp[L[2]];

    float uT[3], uB[3];
    #pragma unroll
    for (int r = 0; r < 3; ++r) {
        uT[r] = __shfl_up_sync(0xffffffffu, aT[r], 1);
        uB[r] = __shfl_up_sync(0xffffffffu, aB[r], 1);
    }
    // lane 0 of reg r takes reg r-1's lane 31 (pair index - 1).
    const float bT1 = __shfl_sync(0xffffffffu, aT[0], 31);
    const float bB1 = __shfl_sync(0xffffffffu, aB[0], 31);
    const float bT2 = __shfl_sync(0xffffffffu, aT[1], 31);
    const float bB2 = __shfl_sync(0xffffffffu, aB[1], 31);
    if (lane == 0) {
        uT[0] = NEGF; uB[0] = NEGF;   // leftmost halo pair: stale by design
        uT[1] = bT1;  uB[1] = bB1;
        uT[2] = bT2;  uB[2] = bB2;
    }

    float nT[3], nB[3];
    #pragma unroll
    for (int r = 0; r < 3; ++r) {
        nT[r] = eT[r] + lse3(aT[r], uB[r], rep[r] ? uT[r] : NEGF);
        nB[r] = eB + lse2(aB[r], aT[r]);
    }
    if (w == 0) {                     // reg0 of warp 0 relays a0
        a0 += eB;
        nT[0] = NEGF;
        nB[0] = (lane == 31) ? a0 : NEGF;
    }
    #pragma unroll
    for (int r = 0; r < 3; ++r) { aT[r] = nT[r]; aB[r] = nB[r]; }
}

__global__ void __launch_bounds__(NTHREADS, 1)
ctc_fused(const float* __restrict__ lp,     // [B, T, V]
          const int* __restrict__ tok,      // [B, S]
          const int* __restrict__ tlens,    // [B]
          const int* __restrict__ slens,    // [B]
          float* __restrict__ out) {
    extern __shared__ float smem[];
    float* buf = smem;                      // [2][CHUNK][VV] = 128 KB
    float* bnd = smem + 2 * CHUNK * VV;     // [2][4][32][2]  = 2 KB

    const int b    = blockIdx.x;
    const int tid  = threadIdx.x;
    const int lane = tid & 31;
    const int w    = tid >> 5;
    const int Tl   = tlens[b];
    const int Sl   = slens[b];
    const float* lpb = lp + (size_t)b * TT * VV;

    // Labels/flags for this thread's 3 pairs: p = 64w - 32 + 32r + lane.
    int L[3]; bool rep[3];
    #pragma unroll
    for (int r = 0; r < 3; ++r) {
        const int p  = 64 * w - 32 + 32 * r + lane;
        const int pc = (p < 0) ? 0 : p;
        L[r] = tok[b * SS + pc];
        const int Lp = (p >= 1) ? tok[b * SS + p - 1] : 0;
        rep[r] = (p >= 1) && (L[r] != Lp);
    }

    // Prologue: stream rows 0..31 (one commit group per row).
    #pragma unroll 1
    for (int r0 = 0; r0 < 2 * CHUNK; ++r0) {
        const float* src = lpb + (size_t)r0 * VV + tid * 8;
        const uint32_t dst =
            (uint32_t)__cvta_generic_to_shared(buf + r0 * VV + tid * 8);
        cp_async16(dst, src);
        cp_async16(dst + 16, src + 4);
        cp_commit();
    }
    cp_wait<CHUNK>();         // rows 0..15 resident
    __syncthreads();

    // t = 0 init.
    float aT[3] = {NEGF, NEGF, NEGF};
    float aB[3] = {NEGF, NEGF, NEGF};
    float a0 = NEGF;
    if (w == 0) {
        a0 = buf[0];                          // alpha[0] = emit(0, blank)
        if (lane == 0)  aT[1] = buf[L[1]];    // alpha[1] = emit(0, tok0)
        if (lane == 31) aB[0] = a0;           // relay slot
    }

    // Chunk 0: steps 1..min(Tl,16)-1 from buffer 0 (nothing to stream).
    {
        const int t1 = (Tl < CHUNK) ? Tl : CHUNK;
        for (int t = 1; t < t1; ++t)
            ctc_step(buf + (t & (CHUNK - 1)) * VV, aT, aB, a0, L, rep, w, lane);
    }

    // Chunks c >= 1.
    for (int c = 1; c * CHUNK < Tl; ++c) {
        // Halo refresh: publish own top 32 pairs (reg2), barrier, read
        // left neighbor's. Barrier also publishes chunk c's cp.asyncs.
        const int pc = (c & 1) * 256;
        bnd[pc + w * 64 + lane * 2 + 0] = aT[2];
        bnd[pc + w * 64 + lane * 2 + 1] = aB[2];
        cp_wait<0>();
        __syncthreads();
        if (w > 0) {
            aT[0] = bnd[pc + (w - 1) * 64 + lane * 2 + 0];
            aB[0] = bnd[pc + (w - 1) * 64 + lane * 2 + 1];
        }

        const int t0 = c * CHUNK;
        const int t1 = (Tl < t0 + CHUNK) ? Tl : (t0 + CHUNK);
        float* curbuf = buf + (c & 1) * CHUNK * VV;
        float* nxtbuf = buf + ((c + 1) & 1) * CHUNK * VV;

        for (int t = t0; t < t1; ++t) {
            const int i = t - t0;
            const int row = t0 + CHUNK + i;   // chunk c+1, row i
            if (row < TT) {
                const float* src = lpb + (size_t)row * VV + tid * 8;
                const uint32_t dst =
                    (uint32_t)__cvta_generic_to_shared(nxtbuf + i * VV + tid * 8);
                cp_async16(dst, src);
                cp_async16(dst + 16, src + 4);
            }
            cp_commit();
            ctc_step(curbuf + i * VV, aT, aB, a0, L, rep, w, lane);
        }
    }

    // Loss from pair q = Sl-1 (own pairs are always exact).
    const int q = Sl - 1;
    if (w == (q >> 6) && lane == (q & 31)) {
        const bool hi = (q >> 5) & 1;
        const float fT = hi ? aT[2] : aT[1];  // alpha[2Sl-1]
        const float fB = hi ? aB[2] : aB[1];  // alpha[2Sl]
        float loss = -lse2(fB, fT);
        if (loss > 1e29f) loss = 0.0f;
        g_losses[b] = loss / (float)Sl;
        __threadfence();
    }
    __syncthreads();

    // Last-block deterministic reduction.
    if (tid == 0) {
        __threadfence();
        const unsigned v = atomicAdd(&g_done, 1u);
        if (v == BB - 1) {
            __threadfence();
            float acc = 0.0f;
            #pragma unroll
            for (int i = 0; i < BB; ++i) acc += g_losses[i];
            out[0] = acc / (float)BB;
            atomicExch(&g_done, 0u);
        }
    }
}

extern "C" void kernel_launch(void* const* d_in, const int* in_sizes, int n_in,
                              void* d_out, int out_size) {
    const float* lp    = (const float*)d_in[0];  // [B,T,V] f32
    const int*   tok   = (const int*)d_in[1];    // [B,S]   i32
    const int*   tlens = (const int*)d_in[2];    // [B]     i32
    const int*   slens = (const int*)d_in[3];    // [B]     i32
    float* out = (float*)d_out;

    const int smem_bytes = (2 * CHUNK * VV + 512) * (int)sizeof(float);
    cudaFuncSetAttribute(ctc_fused, cudaFuncAttributeMaxDynamicSharedMemorySize,
                         smem_bytes);
    ctc_fused<<<BB, NTHREADS, smem_bytes>>>(lp, tok, tlens, slens, out);
}

// round 9
// speedup vs baseline: 1.3790x; 1.1292x over previous
#include <cuda_runtime.h>
#include <cstdint>

// CTC forward loss, B=32, T=2048, V=1024, S=256. Single kernel.
// 32 CTAs x 128 threads (4 warps). NO per-step barrier (halo scheme):
// pairs k=(token s=2k+1, blank s=2k+2), k=0..255. Warp w owns pairs
// [64w,64w+64) in regs r=1,2 and redundantly computes a 32-pair halo
// [64w-32,64w) in reg r=0. Contamination advances 1 pair/step; halos
// refreshed every CHUNK=16 steps at one barrier that also publishes the
// next 16-row cp.async chunk. Per-step exchange is intra-warp shfl only.
// THIS ROUND: emit values (eB, eT[3]) prefetched one step ahead into
// registers + fully unrolled 16-step inner loop, so the scattered smem
// gather (L[r] random -> bank conflicts) overlaps the LSE chain.

#define TT 2048
#define VV 1024
#define SS 256
#define BB 32
#define NEGF (-1e30f)
#define CHUNK 16
#define NTHREADS 128

__device__ float g_losses[BB];
__device__ unsigned int g_done;   // zero-init; self-resetting

__device__ __forceinline__ void cp_async16(uint32_t smem_addr, const void* gmem) {
    asm volatile("cp.async.cg.shared.global [%0], [%1], 16;\n"
                 :: "r"(smem_addr), "l"(gmem));
}
__device__ __forceinline__ void cp_commit() {
    asm volatile("cp.async.commit_group;\n" ::: "memory");
}
template <int N>
__device__ __forceinline__ void cp_wait() {
    asm volatile("cp.async.wait_group %0;\n" :: "n"(N) : "memory");
}

__device__ __forceinline__ float lse2(float a, float b) {
    const float m  = fmaxf(a, b);
    const float lo = fminf(a, b);
    return m + __logf(1.0f + __expf(lo - m));
}
__device__ __forceinline__ float lse3(float x0, float x1, float x2) {
    const float lo1 = fminf(x0, x1);
    const float hi1 = fmaxf(x0, x1);
    const float m   = fmaxf(hi1, x2);
    const float o2  = fminf(hi1, x2);
    return m + __logf(1.0f + __expf(lo1 - m) + __expf(o2 - m));
}

// One DP step with emit values already in registers.
__device__ __forceinline__ void ctc_step(
    const float eB, const float eT[3],
    float aT[3], float aB[3], float& a0,
    const bool rep[3], const int w, const int lane)
{
    float uT[3], uB[3];
    #pragma unroll
    for (int r = 0; r < 3; ++r) {
        uT[r] = __shfl_up_sync(0xffffffffu, aT[r], 1);
        uB[r] = __shfl_up_sync(0xffffffffu, aB[r], 1);
    }
    const float bT1 = __shfl_sync(0xffffffffu, aT[0], 31);
    const float bB1 = __shfl_sync(0xffffffffu, aB[0], 31);
    const float bT2 = __shfl_sync(0xffffffffu, aT[1], 31);
    const float bB2 = __shfl_sync(0xffffffffu, aB[1], 31);
    if (lane == 0) {
        uT[0] = NEGF; uB[0] = NEGF;   // leftmost halo pair: stale by design
        uT[1] = bT1;  uB[1] = bB1;
        uT[2] = bT2;  uB[2] = bB2;
    }

    // Local (shfl-independent) blank updates first — overlap shfl latency.
    float nB[3], nT[3];
    #pragma unroll
    for (int r = 0; r < 3; ++r) nB[r] = eB + lse2(aB[r], aT[r]);
    #pragma unroll
    for (int r = 0; r < 3; ++r)
        nT[r] = eT[r] + lse3(aT[r], uB[r], rep[r] ? uT[r] : NEGF);

    if (w == 0) {                     // reg0 of warp 0 relays a0
        a0 += eB;
        nT[0] = NEGF;
        nB[0] = (lane == 31) ? a0 : NEGF;
    }
    #pragma unroll
    for (int r = 0; r < 3; ++r) { aT[r] = nT[r]; aB[r] = nB[r]; }
}

__global__ void __launch_bounds__(NTHREADS, 1)
ctc_fused(const float* __restrict__ lp,     // [B, T, V]
          const int* __restrict__ tok,      // [B, S]
          const int* __restrict__ tlens,    // [B]
          const int* __restrict__ slens,    // [B]
          float* __restrict__ out) {
    extern __shared__ float smem[];
    float* buf = smem;                      // [2][CHUNK][VV] = 128 KB
    float* bnd = smem + 2 * CHUNK * VV;     // [2][4][32][2]  = 2 KB

    const int b    = blockIdx.x;
    const int tid  = threadIdx.x;
    const int lane = tid & 31;
    const int w    = tid >> 5;
    const int Tl   = tlens[b];
    const int Sl   = slens[b];
    const float* lpb = lp + (size_t)b * TT * VV;

    // Labels/flags for this thread's 3 pairs: p = 64w - 32 + 32r + lane.
    int L[3]; bool rep[3];
    #pragma unroll
    for (int r = 0; r < 3; ++r) {
        const int p  = 64 * w - 32 + 32 * r + lane;
        const int pc = (p < 0) ? 0 : p;
        L[r] = tok[b * SS + pc];
        const int Lp = (p >= 1) ? tok[b * SS + p - 1] : 0;
        rep[r] = (p >= 1) && (L[r] != Lp);
    }

    // Prologue: stream rows 0..31 (one commit group per row).
    #pragma unroll 1
    for (int r0 = 0; r0 < 2 * CHUNK; ++r0) {
        const float* src = lpb + (size_t)r0 * VV + tid * 8;
        const uint32_t dst =
            (uint32_t)__cvta_generic_to_shared(buf + r0 * VV + tid * 8);
        cp_async16(dst, src);
        cp_async16(dst + 16, src + 4);
        cp_commit();
    }
    cp_wait<CHUNK>();         // rows 0..15 resident
    __syncthreads();

    // t = 0 init.
    float aT[3] = {NEGF, NEGF, NEGF};
    float aB[3] = {NEGF, NEGF, NEGF};
    float a0 = NEGF;
    if (w == 0) {
        a0 = buf[0];                          // alpha[0] = emit(0, blank)
        if (lane == 0)  aT[1] = buf[L[1]];    // alpha[1] = emit(0, tok0)
        if (lane == 31) aB[0] = a0;           // relay slot
    }

    // Emit registers for the upcoming step.
    float eB, eT[3];

    // Chunk 0: steps 1..15 (Tl >= 1024, always full). Prefetch dist 1.
    eB = buf[VV];
    eT[0] = buf[VV + L[0]]; eT[1] = buf[VV + L[1]]; eT[2] = buf[VV + L[2]];
    #pragma unroll
    for (int i = 1; i < CHUNK; ++i) {
        float neB = 0.f, neT0 = 0.f, neT1 = 0.f, neT2 = 0.f;
        if (i < CHUNK - 1) {                  // prefetch emits for step i+1
            const float* rp = buf + (i + 1) * VV;
            neB = rp[0]; neT0 = rp[L[0]]; neT1 = rp[L[1]]; neT2 = rp[L[2]];
        }
        ctc_step(eB, eT, aT, aB, a0, rep, w, lane);
        eB = neB; eT[0] = neT0; eT[1] = neT1; eT[2] = neT2;
    }

    // Chunks c >= 1.
    #pragma unroll 1
    for (int c = 1; c * CHUNK < Tl; ++c) {
        // Halo refresh: publish own top 32 pairs (reg2), barrier, read
        // left neighbor's. Barrier also publishes chunk c's cp.asyncs.
        const int pc = (c & 1) * 256;
        bnd[pc + w * 64 + lane * 2 + 0] = aT[2];
        bnd[pc + w * 64 + lane * 2 + 1] = aB[2];
        cp_wait<0>();
        __syncthreads();
        if (w > 0) {
            aT[0] = bnd[pc + (w - 1) * 64 + lane * 2 + 0];
            aB[0] = bnd[pc + (w - 1) * 64 + lane * 2 + 1];
        }

        const int t0 = c * CHUNK;
        float* curbuf = buf + (c & 1) * CHUNK * VV;
        float* nxtbuf = buf + ((c + 1) & 1) * CHUNK * VV;

        // Emits for step t0 (exposed once per chunk).
        eB = curbuf[0];
        eT[0] = curbuf[L[0]]; eT[1] = curbuf[L[1]]; eT[2] = curbuf[L[2]];

        #pragma unroll
        for (int i = 0; i < CHUNK; ++i) {
            const int t = t0 + i;
            // Stream row t0+CHUNK+i into nxtbuf (skip past end).
            const int row = t0 + CHUNK + i;
            if (row < TT) {
                const float* src = lpb + (size_t)row * VV + tid * 8;
                const uint32_t dst =
                    (uint32_t)__cvta_generic_to_shared(nxtbuf + i * VV + tid * 8);
                cp_async16(dst, src);
                cp_async16(dst + 16, src + 4);
            }
            cp_commit();
            // Prefetch emits for step t+1 (within chunk).
            float neB = 0.f, neT0 = 0.f, neT1 = 0.f, neT2 = 0.f;
            if (i < CHUNK - 1) {
                const float* rp = curbuf + (i + 1) * VV;
                neB = rp[0]; neT0 = rp[L[0]]; neT1 = rp[L[1]]; neT2 = rp[L[2]];
            }
            if (t < Tl)                       // CTA-uniform guard
                ctc_step(eB, eT, aT, aB, a0, rep, w, lane);
            eB = neB; eT[0] = neT0; eT[1] = neT1; eT[2] = neT2;
        }
    }

    // Loss from pair q = Sl-1 (own pairs are always exact).
    const int q = Sl - 1;
    if (w == (q >> 6) && lane == (q & 31)) {
        const bool hi = (q >> 5) & 1;
        const float fT = hi ? aT[2] : aT[1];  // alpha[2Sl-1]
        const float fB = hi ? aB[2] : aB[1];  // alpha[2Sl]
        float loss = -lse2(fB, fT);
        if (loss > 1e29f) loss = 0.0f;
        g_losses[b] = loss / (float)Sl;
        __threadfence();
    }
    __syncthreads();

    // Last-block deterministic reduction.
    if (tid == 0) {
        __threadfence();
        const unsigned v = atomicAdd(&g_done, 1u);
        if (v == BB - 1) {
            __threadfence();
            float acc = 0.0f;
            #pragma unroll
            for (int i = 0; i < BB; ++i) acc += g_losses[i];
            out[0] = acc / (float)BB;
            atomicExch(&g_done, 0u);
        }
    }
}

extern "C" void kernel_launch(void* const* d_in, const int* in_sizes, int n_in,
                              void* d_out, int out_size) {
    const float* lp    = (const float*)d_in[0];  // [B,T,V] f32
    const int*   tok   = (const int*)d_in[1];    // [B,S]   i32
    const int*   tlens = (const int*)d_in[2];    // [B]     i32
    const int*   slens = (const int*)d_in[3];    // [B]     i32
    float* out = (float*)d_out;

    const int smem_bytes = (2 * CHUNK * VV + 512) * (int)sizeof(float);
    cudaFuncSetAttribute(ctc_fused, cudaFuncAttributeMaxDynamicSharedMemorySize,
                         smem_bytes);
    ctc_fused<<<BB, NTHREADS, smem_bytes>>>(lp, tok, tlens, slens, out);
}